// round 3
// baseline (speedup 1.0000x reference)
#include <cuda_runtime.h>
#include <math.h>

#define BB 32
#define TT 256
#define EE 256
#define HH 512
#define G4 2048   // 4*HH
#define KK 20
#define START_TAG 18
#define END_TAG 19
#define NEGV (-10000.0f)
#define NBLK 128   // blocks in k_lstm (each handles 4 fwd j + 4 bwd j)

// ---------------- device-global scratch (no dynamic allocation) ----------------
__device__ float g_pre[(size_t)2 * TT * G4 * BB];        // [dir][t][gate][b]  128 MB
__device__ float2 g_hp[2][2][256 * BB];                  // [dir][buf][pair*BB+b]
__device__ float g_lo2[(size_t)2 * TT * HH * BB];        // [dir][t][j][b]  32 MB
__device__ float g_feats[(size_t)BB * TT * KK];          // [b][t][k]
__device__ unsigned g_arrive[2];
__device__ unsigned g_release[2];

// ---------------- tiny helpers ----------------
__device__ __forceinline__ unsigned smem_u32(const void* p) {
    unsigned a;
    asm("{ .reg .u64 t; cvta.to.shared.u64 t, %1; cvt.u32.u64 %0, t; }" : "=r"(a) : "l"(p));
    return a;
}
__device__ __forceinline__ void fma2(unsigned long long& acc, unsigned long long a, unsigned long long b) {
    asm("fma.rn.f32x2 %0, %1, %2, %0;" : "+l"(acc) : "l"(a), "l"(b));
}
__device__ __forceinline__ void lds_v2u64(unsigned addr, unsigned long long& a, unsigned long long& b) {
    asm("ld.shared.v2.u64 {%0,%1}, [%2];" : "=l"(a), "=l"(b) : "r"(addr));
}
__device__ __forceinline__ unsigned long long lds_u64(unsigned addr) {
    unsigned long long v;
    asm("ld.shared.u64 %0, [%1];" : "=l"(v) : "r"(addr));
    return v;
}
__device__ __forceinline__ float hsum4(unsigned long long a, unsigned long long b) {
    float s = __uint_as_float((unsigned)a) + __uint_as_float((unsigned)(a >> 32));
    return s + __uint_as_float((unsigned)b) + __uint_as_float((unsigned)(b >> 32));
}
__device__ __forceinline__ void named_bar(int id) {
    asm volatile("bar.sync %0, 128;" :: "r"(id) : "memory");
}

// ---------------- init: reset barrier state (must run every replay) ----------------
__global__ void k_init() {
    if (threadIdx.x < 2) { g_arrive[threadIdx.x] = 0u; g_release[threadIdx.x] = 0u; }
}

// ---------------- input-projection GEMM, embedding gather fused ----------------
__global__ void __launch_bounds__(256) k_pregemm(
    const int* __restrict__ sent, const float* __restrict__ emb,
    const float* __restrict__ Wf, const float* __restrict__ Wb,
    const float* __restrict__ bf, const float* __restrict__ bb)
{
    extern __shared__ float sm[];
    float* xsT = sm;               // [256][33]
    float* wsT = sm + 256 * 33;    // [256][68]
    __shared__ int stok[BB];

    int t = blockIdx.x, gc = blockIdx.y, dir = blockIdx.z;
    int tid = threadIdx.x;
    if (tid < BB) stok[tid] = sent[tid * TT + t];
    __syncthreads();

    const float* W  = dir ? Wb : Wf;
    const float* bi = dir ? bb : bf;

    for (int i = tid; i < BB * EE; i += 256) {
        int b = i >> 8, e = i & 255;
        xsT[e * 33 + b] = emb[(size_t)stok[b] * EE + e];
    }
    int g0 = gc * 64;
    for (int i = tid; i < 64 * EE; i += 256) {
        int r = i >> 8, e = i & 255;
        wsT[e * 68 + r] = W[(size_t)(g0 + r) * EE + e];
    }
    __syncthreads();

    int tx = tid & 15, ty = tid >> 4;
    int b0 = tx * 2;
    float a00 = 0.f, a01 = 0.f, a10 = 0.f, a11 = 0.f;
    float a20 = 0.f, a21 = 0.f, a30 = 0.f, a31 = 0.f;

#pragma unroll 4
    for (int k = 0; k < EE; k++) {
        float x0 = xsT[k * 33 + b0];
        float x1 = xsT[k * 33 + b0 + 1];
        float4 w = *(const float4*)&wsT[k * 68 + ty * 4];
        a00 = fmaf(w.x, x0, a00); a01 = fmaf(w.x, x1, a01);
        a10 = fmaf(w.y, x0, a10); a11 = fmaf(w.y, x1, a11);
        a20 = fmaf(w.z, x0, a20); a21 = fmaf(w.z, x1, a21);
        a30 = fmaf(w.w, x0, a30); a31 = fmaf(w.w, x1, a31);
    }

    size_t base = (((size_t)dir * TT + t) * G4 + g0) * BB;
    float acc[4][2] = {{a00,a01},{a10,a11},{a20,a21},{a30,a31}};
#pragma unroll
    for (int q = 0; q < 4; q++) {
        int g = ty * 4 + q;
        float bv = bi[g0 + g];
        float2 st = make_float2(acc[q][0] + bv, acc[q][1] + bv);
        *(float2*)&g_pre[base + (size_t)g * BB + b0] = st;
    }
}

// ---------------- persistent BiLSTM recurrence, both dirs fused per block ----------------
// 128 blocks, 256 threads: warps 0-3 = forward j = blk*4+w, warps 4-7 = backward.
// Each half has its own named barrier (1/2) and its own global step barrier, so one
// direction's poll/copy/barrier overlaps the other direction's FFMA2 stream on the SMSP.
__global__ void __launch_bounds__(256) k_lstm(
    const float* __restrict__ Wfhh, const float* __restrict__ Wbhh,
    const float* __restrict__ bfhh, const float* __restrict__ bbhh,
    const int* __restrict__ lengths)
{
    extern __shared__ float sm[];
    // layout (floats): sWf[4][4][512] @0, sWb @8192, shF @16384, shB @32768
    const int jgrp = (int)blockIdx.x;
    const int tid = threadIdx.x;
    const int warp = tid >> 5, lane = tid & 31;
    const int dir = warp >> 2;        // 0 fwd, 1 bwd
    const int wl = warp & 3;
    const int j = jgrp * 4 + wl;
    const int ht = wl * 32 + lane;    // half-local thread id 0..127

    // load weights for this block's 8 (dir,j) rows
    for (int i = tid * 4; i < 16384; i += 1024) {
        int d = i >> 13;
        int r = i & 8191;
        int jl = r >> 11, gate = (r >> 9) & 3, k = r & 511;
        const float* W = d ? Wbhh : Wfhh;
        *(float4*)&sm[i] = *(const float4*)&W[((size_t)(gate * HH + jgrp * 4 + jl)) * HH + k];
    }
    for (int i = tid; i < 2 * HH * BB; i += 256) sm[16384 + i] = 0.0f;
    __syncthreads();
    // halves never __syncthreads again

    const float* bhh = dir ? bbhh : bfhh;
    const float b_i = bhh[0 * HH + j];
    const float b_f = bhh[1 * HH + j];
    const float b_g = bhh[2 * HH + j];
    const float b_o = bhh[3 * HH + j];
    const int mylen = lengths[lane];

    float* shd = sm + 16384 + dir * (HH * BB);
    const unsigned smW = smem_u32(sm) + (unsigned)dir * 32768u + (unsigned)wl * 8192u;
    const unsigned smh = smem_u32(shd);
    const int barid = 1 + dir;

    // prefetch pre-gates for t=0
    float czi, czf, czg, czo;
    int cpos = 0;
    {
        int pos = 0;
        if (dir && 0 < mylen) pos = mylen - 1;
        cpos = pos;
        size_t pb = (((size_t)dir * TT + pos) * G4) * BB + lane;
        czi = __ldcs(&g_pre[pb + (size_t)(0 * HH + j) * BB]);
        czf = __ldcs(&g_pre[pb + (size_t)(1 * HH + j) * BB]);
        czg = __ldcs(&g_pre[pb + (size_t)(2 * HH + j) * BB]);
        czo = __ldcs(&g_pre[pb + (size_t)(3 * HH + j) * BB]);
    }

    float c = 0.0f;
    for (int t = 0; t < TT; t++) {
        // prefetch next-step pre-gates (independent of barrier / h)
        float nzi = 0.f, nzf = 0.f, nzg = 0.f, nzo = 0.f;
        int npos = 0;
        if (t + 1 < TT) {
            npos = t + 1;
            if (dir && (t + 1) < mylen) npos = mylen - 1 - (t + 1);
            size_t pb = (((size_t)dir * TT + npos) * G4) * BB + lane;
            nzi = __ldcs(&g_pre[pb + (size_t)(0 * HH + j) * BB]);
            nzf = __ldcs(&g_pre[pb + (size_t)(1 * HH + j) * BB]);
            nzg = __ldcs(&g_pre[pb + (size_t)(2 * HH + j) * BB]);
            nzo = __ldcs(&g_pre[pb + (size_t)(3 * HH + j) * BB]);
        }

        if (t) {
            if (lane == 0) {
                unsigned r;
                do {
                    asm volatile("ld.acquire.gpu.global.u32 %0, [%1];"
                                 : "=r"(r) : "l"(&g_release[dir]) : "memory");
                } while (r < (unsigned)t);
            }
            __syncwarp();
            const float4* src = (const float4*)&g_hp[dir][t & 1][0];
            float4* dst = (float4*)shd;
#pragma unroll
            for (int q = 0; q < 32; q++) dst[ht + q * 128] = __ldcg(&src[ht + q * 128]);
            named_bar(barid);
        }

        float zi = czi + b_i;
        float zf = czf + b_f;
        float zg = czg + b_g;
        float zo = czo + b_o;

        unsigned long long ai0 = 0, ai1 = 0, af0 = 0, af1 = 0;
        unsigned long long ag0 = 0, ag1 = 0, ao0 = 0, ao1 = 0;
        unsigned hadr = smh + (unsigned)lane * 8u;

#pragma unroll 4
        for (int kq = 0; kq < 128; kq++) {
            unsigned long long wi0, wi1, wf0, wf1, wg0, wg1, wo0, wo1;
            unsigned wa = smW + (unsigned)kq * 16u;
            lds_v2u64(wa,          wi0, wi1);
            lds_v2u64(wa + 2048u,  wf0, wf1);
            lds_v2u64(wa + 4096u,  wg0, wg1);
            lds_v2u64(wa + 6144u,  wo0, wo1);
            unsigned long long h0 = lds_u64(hadr + (unsigned)kq * 512u);
            unsigned long long h1 = lds_u64(hadr + (unsigned)kq * 512u + 256u);
            fma2(ai0, wi0, h0); fma2(af0, wf0, h0); fma2(ag0, wg0, h0); fma2(ao0, wo0, h0);
            fma2(ai1, wi1, h1); fma2(af1, wf1, h1); fma2(ag1, wg1, h1); fma2(ao1, wo1, h1);
        }

        zi += hsum4(ai0, ai1);
        zf += hsum4(af0, af1);
        zg += hsum4(ag0, ag1);
        zo += hsum4(ao0, ao1);

        float gi = 1.0f / (1.0f + expf(-zi));
        float gf = 1.0f / (1.0f + expf(-zf));
        float gg = 1.0f - 2.0f / (expf(2.0f * zg) + 1.0f);
        float go = 1.0f / (1.0f + expf(-zo));

        c = gf * c + gi * gg;
        float h = go * (1.0f - 2.0f / (expf(2.0f * c) + 1.0f));

        // publish h (pair layout for next-step exchange) + lstm output [dir][pos][j][b]
        ((float*)&g_hp[dir][(t + 1) & 1][0])[((j >> 1) * BB + lane) * 2 + (j & 1)] = h;
        g_lo2[(((size_t)dir * TT + cpos) * HH + j) * BB + lane] = h;

        if (t + 1 < TT) {
            named_bar(barid);   // all 4 warps of this half stored h
            if (ht == 0) {
                unsigned old;
                asm volatile("atom.release.gpu.global.add.u32 %0, [%1], %2;"
                             : "=r"(old) : "l"(&g_arrive[dir]), "r"(1u) : "memory");
                if (old == (unsigned)(NBLK * (t + 1) - 1)) {
                    asm volatile("st.release.gpu.global.u32 [%0], %1;"
                                 :: "l"(&g_release[dir]), "r"((unsigned)(t + 1)) : "memory");
                }
            }
        }

        czi = nzi; czf = nzf; czg = nzg; czo = nzo; cpos = npos;
    }
}

// ---------------- feats: per-t GEMM  out[k][b] = Wout[k][:] . h[:][b] ----------------
// grid TT, block 640 (20 warps: warp=k, lane=b).  smem: Wout 80 KB + h slab 128 KB.
__global__ void __launch_bounds__(640) k_feats(
    const float* __restrict__ Wout, const float* __restrict__ bout)
{
    extern __shared__ float sm[];
    float* sW = sm;                 // [20][1024]
    float* sh = sm + 20480;         // [1024][32]
    __shared__ float sb[KK];
    int t = blockIdx.x;
    int tid = threadIdx.x, warp = tid >> 5, lane = tid & 31;

    for (int i = tid * 4; i < KK * 2 * HH; i += 2560)
        *(float4*)&sW[i] = *(const float4*)&Wout[i];
    for (int d = 0; d < 2; d++) {
        const float4* src = (const float4*)&g_lo2[(((size_t)d * TT + t) * HH) * BB];
        float4* dst = (float4*)&sh[d * HH * BB];
        for (int i = tid; i < HH * BB / 4; i += 640) dst[i] = src[i];
    }
    if (tid < KK) sb[tid] = bout[tid];
    __syncthreads();

    float acc = 0.0f;
    const float* wrow = &sW[warp * 2 * HH];
#pragma unroll 8
    for (int jj = 0; jj < 2 * HH; jj += 4) {
        float4 w = *(const float4*)&wrow[jj];
        acc = fmaf(w.x, sh[(jj + 0) * BB + lane], acc);
        acc = fmaf(w.y, sh[(jj + 1) * BB + lane], acc);
        acc = fmaf(w.z, sh[(jj + 2) * BB + lane], acc);
        acc = fmaf(w.w, sh[(jj + 3) * BB + lane], acc);
    }
    g_feats[((size_t)lane * TT + t) * KK + warp] = acc + sb[warp];
}

// ---------------- Viterbi forward + backtrace, one warp per batch ----------------
__global__ void k_viterbi(const float* __restrict__ trans,
                          const int* __restrict__ lengths,
                          float* __restrict__ out)
{
    __shared__ unsigned char bp[TT][KK];
    int b = blockIdx.x;
    int nx = threadIdx.x;
    int len = lengths[b];

    float tr[KK];
#pragma unroll
    for (int p = 0; p < KK; p++) tr[p] = (nx < KK) ? trans[nx * KK + p] : 0.0f;

    float fv = (nx == START_TAG) ? 0.0f : NEGV;
    for (int t = 0; t < len; t++) {
        float best = -INFINITY; int barg = 0;
#pragma unroll
        for (int p = 0; p < KK; p++) {
            float fvp = __shfl_sync(0xffffffffu, fv, p);
            float s = fvp + tr[p];
            if (s > best) { best = s; barg = p; }
        }
        if (nx < KK) {
            bp[t][nx] = (unsigned char)barg;
            fv = best + g_feats[((size_t)b * TT + t) * KK + nx];
        } else {
            fv = NEGV;
        }
        __syncwarp();
    }

    float term = (nx < KK) ? (fv + trans[END_TAG * KK + nx]) : -INFINITY;
    float bestv = -INFINITY; int bt = 0;
#pragma unroll
    for (int p = 0; p < KK; p++) {
        float v = __shfl_sync(0xffffffffu, term, p);
        if (v > bestv) { bestv = v; bt = p; }
    }

    if (nx == 0) {
        out[b] = bestv;
        float* path = out + BB + (size_t)b * (TT + 1);
        path[TT] = (float)bt;
        int cur = bt;
        for (int i = 1; i <= len; i++) {
            cur = bp[len - i][cur];
            path[TT - i] = (float)cur;
        }
        for (int idx = 0; idx < TT - len; idx++) path[idx] = (float)KK;
    }
}

// ---------------- launch ----------------
extern "C" void kernel_launch(void* const* d_in, const int* in_sizes, int n_in,
                              void* d_out, int out_size) {
    const int*   sent  = (const int*)d_in[0];
    const int*   lens  = (const int*)d_in[1];
    const float* emb   = (const float*)d_in[2];
    const float* Wf_ih = (const float*)d_in[3];
    const float* Wf_hh = (const float*)d_in[4];
    const float* bf_ih = (const float*)d_in[5];
    const float* bf_hh = (const float*)d_in[6];
    const float* Wb_ih = (const float*)d_in[7];
    const float* Wb_hh = (const float*)d_in[8];
    const float* bb_ih = (const float*)d_in[9];
    const float* bb_hh = (const float*)d_in[10];
    const float* Wout  = (const float*)d_in[11];
    const float* bout  = (const float*)d_in[12];
    const float* trans = (const float*)d_in[13];
    float* out = (float*)d_out;

    const int smem_pregemm = (256 * 33 + 256 * 68) * 4;
    const int smem_lstm    = (16384 + 2 * HH * BB) * 4;         // 192 KB
    const int smem_feats   = (KK * 2 * HH + 2 * HH * BB) * 4;   // 208 KB
    cudaFuncSetAttribute(k_pregemm, cudaFuncAttributeMaxDynamicSharedMemorySize, smem_pregemm);
    cudaFuncSetAttribute(k_lstm,    cudaFuncAttributeMaxDynamicSharedMemorySize, smem_lstm);
    cudaFuncSetAttribute(k_feats,   cudaFuncAttributeMaxDynamicSharedMemorySize, smem_feats);

    k_init<<<1, 32>>>();

    k_pregemm<<<dim3(TT, G4 / 64, 2), 256, smem_pregemm>>>(sent, emb, Wf_ih, Wb_ih, bf_ih, bb_ih);

    k_lstm<<<NBLK, 256, smem_lstm>>>(Wf_hh, Wb_hh, bf_hh, bb_hh, lens);

    k_feats<<<TT, 640, smem_feats>>>(Wout, bout);

    k_viterbi<<<BB, 32>>>(trans, lens, out);
}

// round 5
// speedup vs baseline: 1.1043x; 1.1043x over previous
#include <cuda_runtime.h>
#include <math.h>

#define BB 32
#define TT 256
#define EE 256
#define HH 512
#define G4 2048   // 4*HH
#define KK 20
#define START_TAG 18
#define END_TAG 19
#define NEGV (-10000.0f)
#define NBLK 128

// ---------------- device-global scratch ----------------
__device__ float g_pre[(size_t)2 * TT * G4 * BB];        // [dir][t][gate][b]
__device__ float2 g_hp[2][2][256 * BB];                  // [dir][buf][pair*BB+b]
__device__ float g_lo2[(size_t)2 * TT * HH * BB];        // [dir][t][j][b]
__device__ float g_feats[(size_t)BB * TT * KK];          // [b][t][k]
__device__ unsigned g_arrive[2];
__device__ unsigned g_release[2];

// ---------------- helpers ----------------
__device__ __forceinline__ unsigned smem_u32(const void* p) {
    unsigned a;
    asm("{ .reg .u64 t; cvta.to.shared.u64 t, %1; cvt.u32.u64 %0, t; }" : "=r"(a) : "l"(p));
    return a;
}
__device__ __forceinline__ void fma2(unsigned long long& acc, unsigned long long a, unsigned long long b) {
    asm("fma.rn.f32x2 %0, %1, %2, %0;" : "+l"(acc) : "l"(a), "l"(b));
}
__device__ __forceinline__ void lds_v2u64(unsigned addr, unsigned long long& a, unsigned long long& b) {
    asm("ld.shared.v2.u64 {%0,%1}, [%2];" : "=l"(a), "=l"(b) : "r"(addr));
}
__device__ __forceinline__ unsigned long long lds_u64(unsigned addr) {
    unsigned long long v;
    asm("ld.shared.u64 %0, [%1];" : "=l"(v) : "r"(addr));
    return v;
}
__device__ __forceinline__ float hsum2(unsigned long long a) {
    return __uint_as_float((unsigned)a) + __uint_as_float((unsigned)(a >> 32));
}
__device__ __forceinline__ void named_bar(int id) {
    asm volatile("bar.sync %0, 128;" :: "r"(id) : "memory");
}

// ---------------- init: reset barrier state (runs inside the graph every replay) ----------------
__global__ void k_init() {
    if (threadIdx.x < 2) { g_arrive[threadIdx.x] = 0u; g_release[threadIdx.x] = 0u; }
}

// ---------------- input-projection GEMM (f32x2), embedding gather fused ----------------
// grid (TT, G4/64, 2), block 256.
__global__ void __launch_bounds__(256) k_pregemm(
    const int* __restrict__ sent, const float* __restrict__ emb,
    const float* __restrict__ Wf, const float* __restrict__ Wb,
    const float* __restrict__ bf, const float* __restrict__ bb)
{
    extern __shared__ float sm[];
    float* xsf = sm;               // x pairs: [ep 0..127][b 0..31][2], stride 68 floats/ep
    float* wsf = sm + 128 * 68;    // w rows:  [r 0..63][e 0..255], stride 258 floats/row
    __shared__ int stok[BB];

    int t = blockIdx.x, gc = blockIdx.y, dir = blockIdx.z;
    int tid = threadIdx.x;
    if (tid < BB) stok[tid] = sent[tid * TT + t];
    __syncthreads();

    const float* W  = dir ? Wb : Wf;
    const float* bi = dir ? bb : bf;

    for (int i = tid; i < BB * EE; i += 256) {
        int b = i >> 8, e = i & 255;
        xsf[(e >> 1) * 68 + b * 2 + (e & 1)] = emb[(size_t)stok[b] * EE + e];
    }
    int g0blk = gc * 64;
    for (int i = tid; i < 64 * EE; i += 256) {
        int r = i >> 8, e = i & 255;
        wsf[r * 258 + e] = W[(size_t)(g0blk + r) * EE + e];
    }
    __syncthreads();

    int tx = tid & 15, ty = tid >> 4;   // tx: batch pair, ty: gate quad
    int b0 = tx * 2;
    int g0 = ty * 4;
    unsigned xb = smem_u32(xsf) + (unsigned)b0 * 8u;
    unsigned wb = smem_u32(wsf) + (unsigned)g0 * 1032u;

    unsigned long long a[4][2];
#pragma unroll
    for (int q = 0; q < 4; q++) { a[q][0] = 0ull; a[q][1] = 0ull; }

#pragma unroll 4
    for (int ep = 0; ep < 128; ep++) {
        unsigned long long x0, x1;
        lds_v2u64(xb + (unsigned)ep * 272u, x0, x1);
        unsigned long long w0 = lds_u64(wb + (unsigned)ep * 8u);
        unsigned long long w1 = lds_u64(wb + 1032u + (unsigned)ep * 8u);
        unsigned long long w2 = lds_u64(wb + 2064u + (unsigned)ep * 8u);
        unsigned long long w3 = lds_u64(wb + 3096u + (unsigned)ep * 8u);
        fma2(a[0][0], w0, x0); fma2(a[0][1], w0, x1);
        fma2(a[1][0], w1, x0); fma2(a[1][1], w1, x1);
        fma2(a[2][0], w2, x0); fma2(a[2][1], w2, x1);
        fma2(a[3][0], w3, x0); fma2(a[3][1], w3, x1);
    }

    size_t base = (((size_t)dir * TT + t) * G4 + g0blk) * BB;
#pragma unroll
    for (int q = 0; q < 4; q++) {
        int g = g0 + q;
        float bv = bi[g0blk + g];
        float2 st = make_float2(hsum2(a[q][0]) + bv, hsum2(a[q][1]) + bv);
        *(float2*)&g_pre[base + (size_t)g * BB + b0] = st;
    }
}

// ---------------- persistent BiLSTM recurrence ----------------
// 128 blocks x 256 threads. warp w: dir=w>>2, p=(w>>1)&1 (j-pair), kh=w&1 (k-half).
// Warp computes partials for j-pair {jgrp*4+p*2, +1} over its k-half, owns j = ...+kh.
// Step barrier: central atomic arrive + release counter per dir (proven in R2/R3).
__global__ void __launch_bounds__(256, 1) k_lstm(
    const float* __restrict__ Wfhh, const float* __restrict__ Wbhh,
    const float* __restrict__ bfhh, const float* __restrict__ bbhh,
    const int* __restrict__ lengths)
{
    extern __shared__ float sm[];
    // floats: [0,16384) interleaved weights; [16384,49152) h (2 dirs); [49152,50176) partials
    const int jgrp = (int)blockIdx.x;
    const int tid = threadIdx.x;
    const int w = tid >> 5, lane = tid & 31;
    const int dir = w >> 2, p = (w >> 1) & 1, kh = w & 1;
    const int jown = jgrp * 4 + p * 2 + kh;
    const int ht = tid & 127;

    // one-time: interleaved weight load
    // sm[wid*2048 + kq*16 + jj*8 + gate*2 + kk] = W_dir[(gate*HH + jgrp*4+p*2+jj)*HH + kh*256 + kq*2 + kk]
    for (int idx = tid; idx < 16384; idx += 256) {
        int ww = idx >> 11;
        int r = idx & 2047;
        int kq = r >> 4, c = r & 15;
        int jj = c >> 3, gate = (c >> 1) & 3, kk = c & 1;
        int d = ww >> 2, pp = (ww >> 1) & 1, kk2 = ww & 1;
        const float* W = d ? Wbhh : Wfhh;
        int jr = jgrp * 4 + pp * 2 + jj;
        int k = kk2 * 256 + kq * 2 + kk;
        sm[idx] = W[((size_t)(gate * HH + jr)) * HH + k];
    }
    for (int i = tid; i < 2 * HH * BB; i += 256) sm[16384 + i] = 0.0f;
    __syncthreads();

    const float* bhh = dir ? bbhh : bfhh;
    float bg[4];
#pragma unroll
    for (int g = 0; g < 4; g++) bg[g] = bhh[g * HH + jown];
    const int mylen = lengths[lane];

    const unsigned smWb = smem_u32(sm) + (unsigned)w * 8192u;
    const unsigned smh  = smem_u32(sm) + 65536u + (unsigned)dir * 65536u + (unsigned)kh * 32768u + (unsigned)lane * 8u;
    float* shd = sm + 16384 + dir * (HH * BB);
    float* part = sm + 49152;
    const int barid = 1 + dir;

    // prefetch pre-gates for t=0 (own j, 4 gates)
    float cz[4];
    int cpos = (dir && 0 < mylen) ? (mylen - 1) : 0;
    {
        size_t pb = (((size_t)dir * TT + cpos) * G4) * BB + lane;
#pragma unroll
        for (int g = 0; g < 4; g++) cz[g] = __ldcs(&g_pre[pb + (size_t)(g * HH + jown) * BB]);
    }

    float c = 0.0f;
    for (int t = 0; t < TT; t++) {
        // prefetch next-step pre-gates (independent of barrier / h)
        float nz[4] = {0.f, 0.f, 0.f, 0.f};
        int npos = 0;
        if (t + 1 < TT) {
            npos = t + 1;
            if (dir && (t + 1) < mylen) npos = mylen - 1 - (t + 1);
            size_t pb = (((size_t)dir * TT + npos) * G4) * BB + lane;
#pragma unroll
            for (int g = 0; g < 4; g++) nz[g] = __ldcs(&g_pre[pb + (size_t)(g * HH + jown) * BB]);
        }

        if (t) {
            if (lane == 0) {
                unsigned r;
                do {
                    asm volatile("ld.acquire.gpu.global.u32 %0, [%1];"
                                 : "=r"(r) : "l"(&g_release[dir]) : "memory");
                } while (r < (unsigned)t);
            }
            __syncwarp();
            const float4* src = (const float4*)&g_hp[dir][t & 1][0];
            float4* dst = (float4*)shd;
#pragma unroll
            for (int q = 0; q < 32; q++) dst[ht + q * 128] = __ldcg(&src[ht + q * 128]);
            named_bar(barid);
        }

        // ---- MAC over this warp's k-half for both j's of the pair ----
        unsigned long long ai0 = 0, af0 = 0, ag0 = 0, ao0 = 0;
        unsigned long long ai1 = 0, af1 = 0, ag1 = 0, ao1 = 0;
#pragma unroll 4
        for (int kq = 0; kq < 128; kq++) {
            unsigned wa = smWb + (unsigned)kq * 64u;
            unsigned long long wi0, wf0, wg0, wo0, wi1, wf1, wg1, wo1;
            lds_v2u64(wa,       wi0, wf0);
            lds_v2u64(wa + 16u, wg0, wo0);
            lds_v2u64(wa + 32u, wi1, wf1);
            lds_v2u64(wa + 48u, wg1, wo1);
            unsigned long long h2 = lds_u64(smh + (unsigned)kq * 256u);
            fma2(ai0, wi0, h2); fma2(af0, wf0, h2); fma2(ag0, wg0, h2); fma2(ao0, wo0, h2);
            fma2(ai1, wi1, h2); fma2(af1, wf1, h2); fma2(ag1, wg1, h2); fma2(ao1, wo1, h2);
        }

        // partner partials: the j this warp does NOT own (jj = 1-kh)
        float po[4], pn[4];
        if (kh == 0) { pn[0] = hsum2(ai1); pn[1] = hsum2(af1); pn[2] = hsum2(ag1); pn[3] = hsum2(ao1);
                       po[0] = hsum2(ai0); po[1] = hsum2(af0); po[2] = hsum2(ag0); po[3] = hsum2(ao0); }
        else         { pn[0] = hsum2(ai0); pn[1] = hsum2(af0); pn[2] = hsum2(ag0); pn[3] = hsum2(ao0);
                       po[0] = hsum2(ai1); po[1] = hsum2(af1); po[2] = hsum2(ag1); po[3] = hsum2(ao1); }
#pragma unroll
        for (int g = 0; g < 4; g++) part[(w * 4 + g) * 32 + lane] = pn[g];
        named_bar(barid);

        float z[4];
#pragma unroll
        for (int g = 0; g < 4; g++)
            z[g] = cz[g] + bg[g] + po[g] + part[((w ^ 1) * 4 + g) * 32 + lane];

        float gi = 1.0f / (1.0f + expf(-z[0]));
        float gf = 1.0f / (1.0f + expf(-z[1]));
        float gg = 1.0f - 2.0f / (expf(2.0f * z[2]) + 1.0f);
        float go = 1.0f / (1.0f + expf(-z[3]));

        c = gf * c + gi * gg;
        float h = go * (1.0f - 2.0f / (expf(2.0f * c) + 1.0f));

        int pairIdx = jgrp * 2 + p;
        ((float*)&g_hp[dir][(t + 1) & 1][pairIdx * BB])[lane * 2 + kh] = h;
        g_lo2[(((size_t)dir * TT + cpos) * HH + jown) * BB + lane] = h;

        if (t + 1 < TT) {
            named_bar(barid);   // all 4 warps of this half stored h
            if (ht == 0) {
                unsigned old;
                asm volatile("atom.release.gpu.global.add.u32 %0, [%1], %2;"
                             : "=r"(old) : "l"(&g_arrive[dir]), "r"(1u) : "memory");
                if (old == (unsigned)(NBLK * (t + 1) - 1)) {
                    asm volatile("st.release.gpu.global.u32 [%0], %1;"
                                 :: "l"(&g_release[dir]), "r"((unsigned)(t + 1)) : "memory");
                }
            }
        }
#pragma unroll
        for (int g = 0; g < 4; g++) cz[g] = nz[g];
        cpos = npos;
    }
}

// ---------------- feats: per-t GEMM  out[k][b] = Wout[k][:] . h[:][b] ----------------
__global__ void __launch_bounds__(640) k_feats(
    const float* __restrict__ Wout, const float* __restrict__ bout)
{
    extern __shared__ float sm[];
    float* sW = sm;                 // [20][1024]
    float* sh = sm + 20480;         // [1024][32]
    __shared__ float sb[KK];
    int t = blockIdx.x;
    int tid = threadIdx.x, warp = tid >> 5, lane = tid & 31;

    for (int i = tid * 4; i < KK * 2 * HH; i += 2560)
        *(float4*)&sW[i] = *(const float4*)&Wout[i];
    for (int d = 0; d < 2; d++) {
        const float4* src = (const float4*)&g_lo2[(((size_t)d * TT + t) * HH) * BB];
        float4* dst = (float4*)&sh[d * HH * BB];
        for (int i = tid; i < HH * BB / 4; i += 640) dst[i] = src[i];
    }
    if (tid < KK) sb[tid] = bout[tid];
    __syncthreads();

    float acc = 0.0f;
    const float* wrow = &sW[warp * 2 * HH];
#pragma unroll 8
    for (int jj = 0; jj < 2 * HH; jj += 4) {
        float4 wv = *(const float4*)&wrow[jj];
        acc = fmaf(wv.x, sh[(jj + 0) * BB + lane], acc);
        acc = fmaf(wv.y, sh[(jj + 1) * BB + lane], acc);
        acc = fmaf(wv.z, sh[(jj + 2) * BB + lane], acc);
        acc = fmaf(wv.w, sh[(jj + 3) * BB + lane], acc);
    }
    g_feats[((size_t)lane * TT + t) * KK + warp] = acc + sb[warp];
}

// ---------------- Viterbi forward + backtrace, one warp per batch ----------------
__global__ void k_viterbi(const float* __restrict__ trans,
                          const int* __restrict__ lengths,
                          float* __restrict__ out)
{
    __shared__ unsigned char bp[TT][KK];
    int b = blockIdx.x;
    int nx = threadIdx.x;
    int len = lengths[b];

    float tr[KK];
#pragma unroll
    for (int p = 0; p < KK; p++) tr[p] = (nx < KK) ? trans[nx * KK + p] : 0.0f;

    float fv = (nx == START_TAG) ? 0.0f : NEGV;
    for (int t = 0; t < len; t++) {
        float best = -INFINITY; int barg = 0;
#pragma unroll
        for (int p = 0; p < KK; p++) {
            float fvp = __shfl_sync(0xffffffffu, fv, p);
            float s = fvp + tr[p];
            if (s > best) { best = s; barg = p; }
        }
        if (nx < KK) {
            bp[t][nx] = (unsigned char)barg;
            fv = best + g_feats[((size_t)b * TT + t) * KK + nx];
        } else {
            fv = NEGV;
        }
        __syncwarp();
    }

    float term = (nx < KK) ? (fv + trans[END_TAG * KK + nx]) : -INFINITY;
    float bestv = -INFINITY; int bt = 0;
#pragma unroll
    for (int p = 0; p < KK; p++) {
        float v = __shfl_sync(0xffffffffu, term, p);
        if (v > bestv) { bestv = v; bt = p; }
    }

    if (nx == 0) {
        out[b] = bestv;
        float* path = out + BB + (size_t)b * (TT + 1);
        path[TT] = (float)bt;
        int cur = bt;
        for (int i = 1; i <= len; i++) {
            cur = bp[len - i][cur];
            path[TT - i] = (float)cur;
        }
        for (int idx = 0; idx < TT - len; idx++) path[idx] = (float)KK;
    }
}

// ---------------- launch ----------------
extern "C" void kernel_launch(void* const* d_in, const int* in_sizes, int n_in,
                              void* d_out, int out_size) {
    const int*   sent  = (const int*)d_in[0];
    const int*   lens  = (const int*)d_in[1];
    const float* emb   = (const float*)d_in[2];
    const float* Wf_ih = (const float*)d_in[3];
    const float* Wf_hh = (const float*)d_in[4];
    const float* bf_ih = (const float*)d_in[5];
    const float* bf_hh = (const float*)d_in[6];
    const float* Wb_ih = (const float*)d_in[7];
    const float* Wb_hh = (const float*)d_in[8];
    const float* bb_ih = (const float*)d_in[9];
    const float* bb_hh = (const float*)d_in[10];
    const float* Wout  = (const float*)d_in[11];
    const float* bout  = (const float*)d_in[12];
    const float* trans = (const float*)d_in[13];
    float* out = (float*)d_out;

    const int smem_pregemm = (128 * 68 + 64 * 258) * 4;          // ~98.5 KB
    const int smem_lstm    = (16384 + 32768 + 1024) * 4;         // ~196 KB
    const int smem_feats   = (KK * 2 * HH + 2 * HH * BB) * 4;    // 208 KB
    cudaFuncSetAttribute(k_pregemm, cudaFuncAttributeMaxDynamicSharedMemorySize, smem_pregemm);
    cudaFuncSetAttribute(k_lstm,    cudaFuncAttributeMaxDynamicSharedMemorySize, smem_lstm);
    cudaFuncSetAttribute(k_feats,   cudaFuncAttributeMaxDynamicSharedMemorySize, smem_feats);

    k_init<<<1, 32>>>();

    k_pregemm<<<dim3(TT, G4 / 64, 2), 256, smem_pregemm>>>(sent, emb, Wf_ih, Wb_ih, bf_ih, bb_ih);

    k_lstm<<<NBLK, 256, smem_lstm>>>(Wf_hh, Wb_hh, bf_hh, bb_hh, lens);

    k_feats<<<TT, 640, smem_feats>>>(Wout, bout);

    k_viterbi<<<BB, 32>>>(trans, lens, out);
}